// round 6
// baseline (speedup 1.0000x reference)
#include <cuda_runtime.h>
#include <cstdint>

// Shape: N=100000, E=1600000, F_in=32, F_out=64, K=3 hops.
#define NMAX 131072
#define EMAX 1703936
#define FIN  32
#define FOUT 64
#define SCAN_T 1024

// Static scratch. Referenced ONLY inside device code.
__device__ __align__(128) float g_h[2][(size_t)NMAX * FIN];
__device__ int   g_cnt[NMAX];        // in-degree (excl. self-loop)
__device__ float g_dinv[NMAX];       // rsqrt(deg incl. self-loop)
__device__ int   g_src[EMAX];        // edge src (int32)
__device__ int   g_dst[EMAX];        // edge dst (int32)
__device__ int   g_rowptr[NMAX + 1]; // CSR row pointers (by dst)
__device__ int   g_cursor[NMAX];     // placement cursors
__device__ int   g_csr_src[EMAX];    // CSR: source node per slot
__device__ float g_csr_w[EMAX];      // CSR: edge weight (norm) per slot

// ---------------------------------------------------------------------------
__global__ void k_cnt_init(int N) {
    int i = blockIdx.x * blockDim.x + threadIdx.x;
    if (i < N) g_cnt[i] = 0;
}

// Edge indices are INT32 on device (JAX x64-disabled downgrades int64->int32;
// harness dtype vocabulary is {float32, int32, bf16}). Defensive range guard:
// out-of-range edges are dropped (wrong-answer signal instead of crash if the
// dtype model is ever wrong).
__global__ void k_edges(const int* __restrict__ ei, int E, int N) {
    int e = blockIdx.x * blockDim.x + threadIdx.x;
    if (e < E) {
        int s = ei[e];
        int d = ei[E + e];
        if ((unsigned)s < (unsigned)N && (unsigned)d < (unsigned)N) {
            g_src[e] = s;
            g_dst[e] = d;
            atomicAdd(&g_cnt[d], 1);
        } else {
            g_src[e] = -1;
            g_dst[e] = -1;
        }
    }
}

// dinv[i] = rsqrt(cnt[i] + 1)   (+1 for the self-loop)
__global__ void k_dinv(int N) {
    int i = blockIdx.x * blockDim.x + threadIdx.x;
    if (i < N) g_dinv[i] = rsqrtf((float)(g_cnt[i] + 1));
}

// Single-block chunked exclusive scan: cnt -> rowptr (+ cursor copy).
__global__ void k_scan(int N) {
    __shared__ int part[SCAN_T];
    int t = threadIdx.x;
    int chunk = (N + SCAN_T - 1) / SCAN_T;
    int beg = t * chunk;
    int end = min(beg + chunk, N);
    int s = 0;
    for (int i = beg; i < end; i++) s += g_cnt[i];
    part[t] = s;
    __syncthreads();
    // Hillis-Steele inclusive scan over 1024 partials
    for (int off = 1; off < SCAN_T; off <<= 1) {
        int v = (t >= off) ? part[t - off] : 0;
        __syncthreads();
        part[t] += v;
        __syncthreads();
    }
    int run = part[t] - s;  // exclusive prefix for this chunk
    for (int i = beg; i < end; i++) {
        g_rowptr[i] = run;
        g_cursor[i] = run;
        run += g_cnt[i];
    }
    if (t == SCAN_T - 1) g_rowptr[N] = run;
}

// Place edges into CSR slots (int atomics for slot claim).
__global__ void k_place(int E) {
    int e = blockIdx.x * blockDim.x + threadIdx.x;
    if (e < E) {
        int s = g_src[e];
        int d = g_dst[e];
        if (s >= 0) {
            int pos = atomicAdd(&g_cursor[d], 1);
            g_csr_src[pos] = s;
            g_csr_w[pos] = g_dinv[s] * g_dinv[d];
        }
    }
}

// One propagation hop (pull/gather, NO float atomics):
// out[d][:] = dinv[d]^2 * in[d][:] + sum_{e: dst=d} w_e * in[src_e][:]
// 8 lanes per dst node, each lane owns one float4 of the 128B row.
// srcSel: -1 -> x (harness input), 0/1 -> g_h[srcSel]. dstSel: 0/1.
__global__ void k_hop(const float4* __restrict__ x, int srcSel, int dstSel, int N) {
    const float4* in  = (srcSel < 0) ? x : (const float4*)g_h[srcSel];
    float4*       out = (float4*)g_h[dstSel];
    int t = blockIdx.x * blockDim.x + threadIdx.x;
    int d = t >> 3;
    int j = t & 7;
    if (d >= N) return;

    float dv = g_dinv[d];
    float c = dv * dv;
    float4 a = __ldg(&in[(size_t)d * 8 + j]);
    float accx = c * a.x, accy = c * a.y, accz = c * a.z, accw = c * a.w;

    int beg = g_rowptr[d];
    int end = g_rowptr[d + 1];
#pragma unroll 4
    for (int i = beg; i < end; i++) {
        int   s = g_csr_src[i];
        float w = g_csr_w[i];
        float4 v = __ldg(&in[(size_t)s * 8 + j]);
        accx += w * v.x;
        accy += w * v.y;
        accz += w * v.z;
        accw += w * v.w;
    }
    out[(size_t)d * 8 + j] = make_float4(accx, accy, accz, accw);
}

// out[n][o] = sum_k h[n][k] * W[o][k] + b[o]; W staged in smem.
__global__ void k_gemm(int srcSel, const float* __restrict__ W,
                       const float* __restrict__ b, float* __restrict__ out, int N) {
    const float* h = g_h[srcSel];
    __shared__ float ws[FOUT * FIN];
    __shared__ float bs[FOUT];
    int tid = threadIdx.x;
    for (int i = tid; i < FOUT * FIN; i += blockDim.x) ws[i] = W[i];
    if (tid < FOUT) bs[tid] = b[tid];
    __syncthreads();

    int g = blockIdx.x * blockDim.x + tid;
    int n = g >> 1;
    int half = g & 1;
    if (n >= N) return;

    float xr[FIN];
    const float4* hp = (const float4*)(h + (size_t)n * FIN);
#pragma unroll
    for (int k = 0; k < FIN / 4; k++) {
        float4 v = hp[k];
        xr[4 * k + 0] = v.x; xr[4 * k + 1] = v.y;
        xr[4 * k + 2] = v.z; xr[4 * k + 3] = v.w;
    }

    const float* wbase = ws + half * 32 * FIN;
    float acc[32];
#pragma unroll
    for (int o = 0; o < 32; o++) {
        float a = bs[half * 32 + o];
        const float4* wr = (const float4*)(wbase + o * FIN);
#pragma unroll
        for (int k = 0; k < FIN / 4; k++) {
            float4 w4 = wr[k];
            a += xr[4 * k + 0] * w4.x;
            a += xr[4 * k + 1] * w4.y;
            a += xr[4 * k + 2] * w4.z;
            a += xr[4 * k + 3] * w4.w;
        }
        acc[o] = a;
    }

    float4* op = (float4*)(out + (size_t)n * FOUT + half * 32);
#pragma unroll
    for (int q = 0; q < 8; q++)
        op[q] = make_float4(acc[4 * q], acc[4 * q + 1], acc[4 * q + 2], acc[4 * q + 3]);
}

// ---------------------------------------------------------------------------
extern "C" void kernel_launch(void* const* d_in, const int* in_sizes, int n_in,
                              void* d_out, int out_size) {
    const float* x  = (const float*)d_in[0];   // [N, 32] f32
    const int*   ei = (const int*)d_in[1];     // [2, E] int32 (JAX x64 disabled)
    const float* W  = (const float*)d_in[2];   // [64, 32] f32
    const float* b  = (const float*)d_in[3];   // [64] f32
    float*       out = (float*)d_out;          // [N, 64] f32

    const int N = in_sizes[0] / FIN;
    const int E = in_sizes[1] / 2;

    const int TB = 256;
    const int nBlocksN = (N + TB - 1) / TB;
    const int nBlocksE = (E + TB - 1) / TB;

    // --- CSR build (per launch; deterministic work) ---
    k_cnt_init<<<nBlocksN, TB>>>(N);
    k_edges<<<nBlocksE, TB>>>(ei, E, N);
    k_dinv<<<nBlocksN, TB>>>(N);
    k_scan<<<1, SCAN_T>>>(N);
    k_place<<<nBlocksE, TB>>>(E);

    // --- K=3 hops (pull gather, ping-pong g_h[0]/g_h[1]) ---
    const int hopBlocks = (N * 8 + TB - 1) / TB;
    k_hop<<<hopBlocks, TB>>>((const float4*)x, -1, 0, N);  // x      -> g_h[0]
    k_hop<<<hopBlocks, TB>>>((const float4*)x,  0, 1, N);  // g_h[0] -> g_h[1]
    k_hop<<<hopBlocks, TB>>>((const float4*)x,  1, 0, N);  // g_h[1] -> g_h[0]

    // --- final linear transform ---
    k_gemm<<<(N * 2 + TB - 1) / TB, TB>>>(0, W, b, out, N);
}

// round 7
// speedup vs baseline: 1.9367x; 1.9367x over previous
#include <cuda_runtime.h>
#include <cstdint>

// Shape: N=100000, E=1600000, F_in=32, F_out=64, K=3 hops.
#define NMAX 131072
#define EMAX 1703936
#define FIN  32
#define FOUT 64
#define SB   256   // scan blocks (phase A/C grid, phase B block size)

// Static scratch. Referenced ONLY inside device code.
__device__ __align__(128) float g_h[2][(size_t)NMAX * FIN];
__device__ int   g_cnt[NMAX];        // in-degree (excl. self-loop)
__device__ float g_dinv[NMAX];       // rsqrt(deg incl. self-loop)
__device__ int   g_src[EMAX];        // edge src (int32)
__device__ int   g_dst[EMAX];        // edge dst (int32)
__device__ int   g_rowptr[NMAX + 1]; // CSR row pointers (by dst)
__device__ int   g_cursor[NMAX];     // placement cursors
__device__ int   g_csr_src[EMAX];    // CSR: source node per slot
__device__ float g_csr_w[EMAX];      // CSR: edge weight (norm) per slot
__device__ int   g_bsum[SB];         // per-block tile sums (scan phase A->B)

// ---------------------------------------------------------------------------
__global__ void k_cnt_init(int N) {
    int i = blockIdx.x * blockDim.x + threadIdx.x;
    if (i < N) g_cnt[i] = 0;
}

// int32 edges (JAX x64-disabled); range guard keeps bad data a rel_err signal.
__global__ void k_edges(const int* __restrict__ ei, int E, int N) {
    int e = blockIdx.x * blockDim.x + threadIdx.x;
    if (e < E) {
        int s = ei[e];
        int d = ei[E + e];
        if ((unsigned)s < (unsigned)N && (unsigned)d < (unsigned)N) {
            g_src[e] = s;
            g_dst[e] = d;
            atomicAdd(&g_cnt[d], 1);
        } else {
            g_src[e] = -1;
            g_dst[e] = -1;
        }
    }
}

// dinv[i] = rsqrt(cnt[i] + 1)   (+1 for the self-loop)
__global__ void k_dinv(int N) {
    int i = blockIdx.x * blockDim.x + threadIdx.x;
    if (i < N) g_dinv[i] = rsqrtf((float)(g_cnt[i] + 1));
}

// ---- Hierarchical exclusive scan of g_cnt -> g_rowptr / g_cursor ----------
// Phase A: each of SB blocks tree-reduces its tile of counts -> g_bsum[b].
__global__ void k_scan_a(int N) {
    __shared__ int sh[256];
    int b = blockIdx.x, t = threadIdx.x;
    int tile = (N + SB - 1) / SB;
    int beg = b * tile, end = min(beg + tile, N);
    int s = 0;
    for (int i = beg + t; i < end; i += 256) s += g_cnt[i];
    sh[t] = s;
    __syncthreads();
#pragma unroll
    for (int off = 128; off > 0; off >>= 1) {
        if (t < off) sh[t] += sh[t + off];
        __syncthreads();
    }
    if (t == 0) g_bsum[b] = sh[0];
}

// Phase B: one block exclusive-scans the SB block sums; writes total rowptr[N].
__global__ void k_scan_b(int N) {
    __shared__ int sh[SB];
    int t = threadIdx.x;
    int v = g_bsum[t];
    sh[t] = v;
    __syncthreads();
#pragma unroll
    for (int off = 1; off < SB; off <<= 1) {
        int u = (t >= off) ? sh[t - off] : 0;
        __syncthreads();
        sh[t] += u;
        __syncthreads();
    }
    g_bsum[t] = sh[t] - v;                 // exclusive block offset
    if (t == SB - 1) g_rowptr[N] = sh[t];  // grand total
}

// Phase C: per-block local exclusive scan (+block offset), write rowptr/cursor.
__global__ void k_scan_c(int N) {
    __shared__ int sh[256];
    int b = blockIdx.x, t = threadIdx.x;
    int tile = (N + SB - 1) / SB;
    int beg = b * tile, end = min(beg + tile, N);
    int chunk = (tile + 255) / 256;
    int cbeg = beg + t * chunk;
    int cend = min(cbeg + chunk, end);
    int s = 0;
    for (int i = cbeg; i < cend; i++) s += g_cnt[i];
    sh[t] = s;
    __syncthreads();
#pragma unroll
    for (int off = 1; off < 256; off <<= 1) {
        int u = (t >= off) ? sh[t - off] : 0;
        __syncthreads();
        sh[t] += u;
        __syncthreads();
    }
    int run = g_bsum[b] + sh[t] - s;       // global exclusive prefix
    for (int i = cbeg; i < cend; i++) {
        g_rowptr[i] = run;
        g_cursor[i] = run;
        run += g_cnt[i];
    }
}

// Place edges into CSR slots (int atomics for slot claim).
__global__ void k_place(int E) {
    int e = blockIdx.x * blockDim.x + threadIdx.x;
    if (e < E) {
        int s = g_src[e];
        int d = g_dst[e];
        if (s >= 0) {
            int pos = atomicAdd(&g_cursor[d], 1);
            g_csr_src[pos] = s;
            g_csr_w[pos] = g_dinv[s] * g_dinv[d];
        }
    }
}

// One propagation hop (pull/gather, NO float atomics):
// out[d][:] = dinv[d]^2 * in[d][:] + sum_{e: dst=d} w_e * in[src_e][:]
// 8 lanes per dst node, each lane owns one float4 of the 128B row.
__global__ void k_hop(const float4* __restrict__ x, int srcSel, int dstSel, int N) {
    const float4* in  = (srcSel < 0) ? x : (const float4*)g_h[srcSel];
    float4*       out = (float4*)g_h[dstSel];
    int t = blockIdx.x * blockDim.x + threadIdx.x;
    int d = t >> 3;
    int j = t & 7;
    if (d >= N) return;

    float dv = g_dinv[d];
    float c = dv * dv;
    float4 a = __ldg(&in[(size_t)d * 8 + j]);
    float accx = c * a.x, accy = c * a.y, accz = c * a.z, accw = c * a.w;

    int beg = g_rowptr[d];
    int end = g_rowptr[d + 1];
#pragma unroll 4
    for (int i = beg; i < end; i++) {
        int   s = g_csr_src[i];
        float w = g_csr_w[i];
        float4 v = __ldg(&in[(size_t)s * 8 + j]);
        accx += w * v.x;
        accy += w * v.y;
        accz += w * v.z;
        accw += w * v.w;
    }
    out[(size_t)d * 8 + j] = make_float4(accx, accy, accz, accw);
}

// out[n][o] = sum_k h[n][k] * W[o][k] + b[o]; W staged in smem.
__global__ void k_gemm(int srcSel, const float* __restrict__ W,
                       const float* __restrict__ b, float* __restrict__ out, int N) {
    const float* h = g_h[srcSel];
    __shared__ float ws[FOUT * FIN];
    __shared__ float bs[FOUT];
    int tid = threadIdx.x;
    for (int i = tid; i < FOUT * FIN; i += blockDim.x) ws[i] = W[i];
    if (tid < FOUT) bs[tid] = b[tid];
    __syncthreads();

    int g = blockIdx.x * blockDim.x + tid;
    int n = g >> 1;
    int half = g & 1;
    if (n >= N) return;

    float xr[FIN];
    const float4* hp = (const float4*)(h + (size_t)n * FIN);
#pragma unroll
    for (int k = 0; k < FIN / 4; k++) {
        float4 v = hp[k];
        xr[4 * k + 0] = v.x; xr[4 * k + 1] = v.y;
        xr[4 * k + 2] = v.z; xr[4 * k + 3] = v.w;
    }

    const float* wbase = ws + half * 32 * FIN;
    float acc[32];
#pragma unroll
    for (int o = 0; o < 32; o++) {
        float a = bs[half * 32 + o];
        const float4* wr = (const float4*)(wbase + o * FIN);
#pragma unroll
        for (int k = 0; k < FIN / 4; k++) {
            float4 w4 = wr[k];
            a += xr[4 * k + 0] * w4.x;
            a += xr[4 * k + 1] * w4.y;
            a += xr[4 * k + 2] * w4.z;
            a += xr[4 * k + 3] * w4.w;
        }
        acc[o] = a;
    }

    float4* op = (float4*)(out + (size_t)n * FOUT + half * 32);
#pragma unroll
    for (int q = 0; q < 8; q++)
        op[q] = make_float4(acc[4 * q], acc[4 * q + 1], acc[4 * q + 2], acc[4 * q + 3]);
}

// ---------------------------------------------------------------------------
extern "C" void kernel_launch(void* const* d_in, const int* in_sizes, int n_in,
                              void* d_out, int out_size) {
    const float* x  = (const float*)d_in[0];   // [N, 32] f32
    const int*   ei = (const int*)d_in[1];     // [2, E] int32
    const float* W  = (const float*)d_in[2];   // [64, 32] f32
    const float* b  = (const float*)d_in[3];   // [64] f32
    float*       out = (float*)d_out;          // [N, 64] f32

    const int N = in_sizes[0] / FIN;
    const int E = in_sizes[1] / 2;

    const int TB = 256;
    const int nBlocksN = (N + TB - 1) / TB;
    const int nBlocksE = (E + TB - 1) / TB;

    // --- CSR build ---
    k_cnt_init<<<nBlocksN, TB>>>(N);
    k_edges<<<nBlocksE, TB>>>(ei, E, N);
    k_dinv<<<nBlocksN, TB>>>(N);
    k_scan_a<<<SB, 256>>>(N);
    k_scan_b<<<1, SB>>>(N);
    k_scan_c<<<SB, 256>>>(N);
    k_place<<<nBlocksE, TB>>>(E);

    // --- K=3 hops (pull gather, ping-pong g_h[0]/g_h[1]) ---
    const int hopBlocks = (N * 8 + TB - 1) / TB;
    k_hop<<<hopBlocks, TB>>>((const float4*)x, -1, 0, N);  // x      -> g_h[0]
    k_hop<<<hopBlocks, TB>>>((const float4*)x,  0, 1, N);  // g_h[0] -> g_h[1]
    k_hop<<<hopBlocks, TB>>>((const float4*)x,  1, 0, N);  // g_h[1] -> g_h[0]

    // --- final linear transform ---
    k_gemm<<<(N * 2 + TB - 1) / TB, TB>>>(0, W, b, out, N);
}